// round 1
// baseline (speedup 1.0000x reference)
#include <cuda_runtime.h>

#define BATCH 8
#define CH    128
#define HH    48
#define WW    64
#define NN    (HH*WW)   // 3072

// Scratch: transposed q and k, layout [B][C][N] (same as feature layout)
__device__ float g_qT[BATCH*CH*NN];
__device__ float g_kT[BATCH*CH*NN];

// ---------------------------------------------------------------------------
// Flash softmax-attention with 2-column V.
// Scores(n,m) = sum_c AT[b][c][n] * BT[b][c][m] * (1/sqrt(C))
// MODE 0 (correlation): V[m] = (m%W, m/W); output = acc/L - grid(n)  -> flow_pred
// MODE 1 (self-attn):   V[m] = (vsrc[b][0][m], vsrc[b][1][m]); out = acc/L -> flow
// Tile: 64 queries x 64 keys, 256 threads, 4x4 micro-tile per thread.
// Smem: As[128][64] (persistent per block) + Bs[64][64] (c-chunked) = 48 KB.
// ---------------------------------------------------------------------------
template<int MODE>
__global__ void __launch_bounds__(256) flash_kernel(
    const float* __restrict__ AT, const float* __restrict__ BT,
    const float* __restrict__ vsrc, float* __restrict__ out)
{
    __shared__ float As[128][64];
    __shared__ float Bs[64][64];

    const int b  = blockIdx.y;
    const int n0 = blockIdx.x * 64;
    const int t  = threadIdx.x;
    const int tx = t & 15;   // key group   (4 keys each)
    const int ty = t >> 4;   // query group (4 queries each)

    const float* Ab = AT + (size_t)b * CH * NN;
    const float* Bb = BT + (size_t)b * CH * NN;

    // Load the full query tile once: As[c][q_local]
    for (int idx = t; idx < 128*16; idx += 256) {
        int r = idx >> 4, g = idx & 15;
        *(float4*)(&As[r][g*4]) = *(const float4*)(Ab + (size_t)r*NN + n0 + g*4);
    }

    float M[4], L[4], AX[4], AY[4];
    #pragma unroll
    for (int i = 0; i < 4; i++) { M[i] = -1e30f; L[i] = 0.f; AX[i] = 0.f; AY[i] = 0.f; }

    const float scale = 0.088388347648318447f; // 1/sqrt(128)

    for (int m0 = 0; m0 < NN; m0 += 64) {
        float S[4][4];
        #pragma unroll
        for (int i = 0; i < 4; i++)
            #pragma unroll
            for (int j = 0; j < 4; j++) S[i][j] = 0.f;

        // Two c-chunks of 64 so Bs fits alongside the persistent As (48 KB total)
        #pragma unroll
        for (int ch = 0; ch < 2; ch++) {
            __syncthreads();   // protect Bs from previous consumers
            for (int idx = t; idx < 64*16; idx += 256) {
                int r = idx >> 4, g = idx & 15;
                *(float4*)(&Bs[r][g*4]) =
                    *(const float4*)(Bb + (size_t)(ch*64 + r)*NN + m0 + g*4);
            }
            __syncthreads();
            #pragma unroll 4
            for (int c = 0; c < 64; c++) {
                float4 a = *(const float4*)(&As[ch*64 + c][ty*4]);
                float4 v = *(const float4*)(&Bs[c][tx*4]);
                S[0][0] += a.x*v.x; S[0][1] += a.x*v.y; S[0][2] += a.x*v.z; S[0][3] += a.x*v.w;
                S[1][0] += a.y*v.x; S[1][1] += a.y*v.y; S[1][2] += a.y*v.z; S[1][3] += a.y*v.w;
                S[2][0] += a.z*v.x; S[2][1] += a.z*v.y; S[2][2] += a.z*v.z; S[2][3] += a.z*v.w;
                S[3][0] += a.w*v.x; S[3][1] += a.w*v.y; S[3][2] += a.w*v.z; S[3][3] += a.w*v.w;
            }
        }

        // V values for this thread's 4 keys
        float vx[4], vy[4];
        if (MODE == 0) {
            #pragma unroll
            for (int j = 0; j < 4; j++) {
                int m = m0 + tx*4 + j;
                vx[j] = (float)(m & (WW-1));
                vy[j] = (float)(m >> 6);
            }
        } else {
            const float* vp = vsrc + (size_t)b*2*NN + m0 + tx*4;
            float4 x4 = *(const float4*)vp;
            float4 y4 = *(const float4*)(vp + NN);
            vx[0]=x4.x; vx[1]=x4.y; vx[2]=x4.z; vx[3]=x4.w;
            vy[0]=y4.x; vy[1]=y4.y; vy[2]=y4.z; vy[3]=y4.w;
        }

        // Online softmax update. Row max reduced across the 16 tx lanes;
        // L / AX / AY stay per-lane partial (reduced once at the end).
        #pragma unroll
        for (int i = 0; i < 4; i++) {
            float s0 = S[i][0]*scale, s1 = S[i][1]*scale;
            float s2 = S[i][2]*scale, s3 = S[i][3]*scale;
            float mx = fmaxf(fmaxf(s0, s1), fmaxf(s2, s3));
            #pragma unroll
            for (int o = 8; o > 0; o >>= 1)
                mx = fmaxf(mx, __shfl_xor_sync(0xffffffffu, mx, o));
            float newM = fmaxf(M[i], mx);
            float corr = __expf(M[i] - newM);
            float p0 = __expf(s0 - newM), p1 = __expf(s1 - newM);
            float p2 = __expf(s2 - newM), p3 = __expf(s3 - newM);
            L[i]  = L[i]*corr  + (p0 + p1 + p2 + p3);
            AX[i] = AX[i]*corr + (p0*vx[0] + p1*vx[1] + p2*vx[2] + p3*vx[3]);
            AY[i] = AY[i]*corr + (p0*vy[0] + p1*vy[1] + p2*vy[2] + p3*vy[3]);
            M[i] = newM;
        }
    }

    // Final cross-lane reduction of partials (all lanes share the same M[i])
    #pragma unroll
    for (int i = 0; i < 4; i++) {
        #pragma unroll
        for (int o = 8; o > 0; o >>= 1) {
            L[i]  += __shfl_xor_sync(0xffffffffu, L[i],  o);
            AX[i] += __shfl_xor_sync(0xffffffffu, AX[i], o);
            AY[i] += __shfl_xor_sync(0xffffffffu, AY[i], o);
        }
    }
    if (tx == 0) {
        #pragma unroll
        for (int i = 0; i < 4; i++) {
            int n = n0 + ty*4 + i;
            float fx = AX[i] / L[i];
            float fy = AY[i] / L[i];
            if (MODE == 0) { fx -= (float)(n & (WW-1)); fy -= (float)(n >> 6); }
            out[(size_t)b*2*NN + n]      = fx;
            out[(size_t)b*2*NN + NN + n] = fy;
        }
    }
}

// ---------------------------------------------------------------------------
// Projection: Y[n][co] = sum_ci XT[b][ci][n] * W[co][ci] + bias[co]
// XT layout [B][C][N]; output written TRANSPOSED: YT[b][co][n].
// Tile: 64 n x 64 co, c_in chunked by 64. Smem 32 KB.
// ---------------------------------------------------------------------------
__global__ void __launch_bounds__(256) proj_kernel(
    const float* __restrict__ XT, const float* __restrict__ Wt,
    const float* __restrict__ bias, float* __restrict__ YT)
{
    __shared__ float Xs[64][64];
    __shared__ float Ws[64][64];

    const int b   = blockIdx.z;
    const int n0  = blockIdx.x * 64;
    const int co0 = blockIdx.y * 64;
    const int t   = threadIdx.x;
    const int tx  = t & 15;   // n group
    const int ty  = t >> 4;   // co group

    const float* Xb = XT + (size_t)b * CH * NN;

    float acc[4][4];
    #pragma unroll
    for (int i = 0; i < 4; i++)
        #pragma unroll
        for (int j = 0; j < 4; j++) acc[i][j] = 0.f;

    #pragma unroll
    for (int ch = 0; ch < 2; ch++) {
        __syncthreads();
        for (int idx = t; idx < 64*16; idx += 256) {
            int r = idx >> 4, g = idx & 15;
            *(float4*)(&Xs[r][g*4]) =
                *(const float4*)(Xb + (size_t)(ch*64 + r)*NN + n0 + g*4);
        }
        // Ws[ci][co] = W[co0+co][ch*64+ci]  (transpose on load; tiny, once)
        for (int idx = t; idx < 64*16; idx += 256) {
            int co = idx >> 4, g = idx & 15;
            float4 w4 = *(const float4*)(Wt + (size_t)(co0 + co)*CH + ch*64 + g*4);
            Ws[g*4+0][co] = w4.x; Ws[g*4+1][co] = w4.y;
            Ws[g*4+2][co] = w4.z; Ws[g*4+3][co] = w4.w;
        }
        __syncthreads();
        #pragma unroll 4
        for (int c = 0; c < 64; c++) {
            float4 xa = *(const float4*)(&Xs[c][tx*4]);
            float4 wa = *(const float4*)(&Ws[c][ty*4]);
            acc[0][0] += wa.x*xa.x; acc[0][1] += wa.x*xa.y; acc[0][2] += wa.x*xa.z; acc[0][3] += wa.x*xa.w;
            acc[1][0] += wa.y*xa.x; acc[1][1] += wa.y*xa.y; acc[1][2] += wa.y*xa.z; acc[1][3] += wa.y*xa.w;
            acc[2][0] += wa.z*xa.x; acc[2][1] += wa.z*xa.y; acc[2][2] += wa.z*xa.z; acc[2][3] += wa.z*xa.w;
            acc[3][0] += wa.w*xa.x; acc[3][1] += wa.w*xa.y; acc[3][2] += wa.w*xa.z; acc[3][3] += wa.w*xa.w;
        }
    }

    #pragma unroll
    for (int i = 0; i < 4; i++) {
        int co = co0 + ty*4 + i;
        float bv = bias[co];
        float4 o;
        o.x = acc[i][0] + bv; o.y = acc[i][1] + bv;
        o.z = acc[i][2] + bv; o.w = acc[i][3] + bv;
        *(float4*)(YT + (size_t)b*CH*NN + (size_t)co*NN + n0 + tx*4) = o;
    }
}

// ---------------------------------------------------------------------------
// Inputs (metadata order): feature0, feature1, q_w, q_b, k_w, k_b, scale_idx
// Output: [flow (B*2*H*W) | flow_pred (B*2*H*W)] float32
// ---------------------------------------------------------------------------
extern "C" void kernel_launch(void* const* d_in, const int* in_sizes, int n_in,
                              void* d_out, int out_size)
{
    const float* f0 = (const float*)d_in[0];
    const float* f1 = (const float*)d_in[1];
    const float* qw = (const float*)d_in[2];
    const float* qb = (const float*)d_in[3];
    const float* kw = (const float*)d_in[4];
    const float* kb = (const float*)d_in[5];

    float* out       = (float*)d_out;
    float* flow      = out;                      // [B,2,H,W]
    float* flow_pred = out + (size_t)BATCH*2*NN; // [B,2,H,W]

    void *qT_raw, *kT_raw;
    cudaGetSymbolAddress(&qT_raw, g_qT);
    cudaGetSymbolAddress(&kT_raw, g_kT);
    float* qT = (float*)qT_raw;
    float* kT = (float*)kT_raw;

    dim3 fgrid(NN/64, BATCH);
    dim3 pgrid(NN/64, CH/64, BATCH);

    // Stage 1: global correlation softmax -> flow regression (flow_pred)
    flash_kernel<0><<<fgrid, 256>>>(f0, f1, nullptr, flow_pred);
    // Stage 2: q = f0 @ q_w^T + q_b ; k = q @ k_w^T + k_b  (both stored [B][C][N])
    proj_kernel<<<pgrid, 256>>>(f0, qw, qb, qT);
    proj_kernel<<<pgrid, 256>>>(qT, kw, kb, kT);
    // Stage 3: self-attention propagation of flow_pred -> flow
    flash_kernel<1><<<fgrid, 256>>>(qT, kT, flow_pred, flow);
}

// round 3
// speedup vs baseline: 3.8204x; 3.8204x over previous
#include <cuda_runtime.h>
#include <cuda_fp16.h>
#include <cstdint>

#define BATCH 8
#define CH    128
#define HH    48
#define WW    64
#define NN    (HH*WW)   // 3072

// ---------------------------------------------------------------------------
// Scratch (__device__ globals; no allocation allowed)
// ---------------------------------------------------------------------------
__device__ float  g_qT [BATCH*CH*NN];   // q fp32 [B][C][N] (input to proj2)
__device__ float  g_kT [BATCH*CH*NN];   // k fp32 [B][C][N] (unused downstream)
__device__ __half g_f0h[BATCH*NN*CH];   // f0 fp16 [B][N][C]
__device__ __half g_f1h[BATCH*NN*CH];   // f1 fp16 [B][N][C]
__device__ __half g_qh [BATCH*NN*CH];   // q  fp16 [B][N][C]
__device__ __half g_kh [BATCH*NN*CH];   // k  fp16 [B][N][C]

// ---------------------------------------------------------------------------
// Base-ISA warp MMA helpers (sm_80+; no sm_103a-only instructions!)
// ---------------------------------------------------------------------------
__device__ __forceinline__ uint32_t smem_u32(const void* p) {
    uint32_t a;
    asm("{ .reg .u64 t; cvta.to.shared.u64 t, %1; cvt.u32.u64 %0, t; }" : "=r"(a) : "l"(p));
    return a;
}
__device__ __forceinline__ void ldsm4(uint32_t* r, uint32_t addr) {
    asm volatile("ldmatrix.sync.aligned.m8n8.x4.shared.b16 {%0,%1,%2,%3}, [%4];"
        : "=r"(r[0]), "=r"(r[1]), "=r"(r[2]), "=r"(r[3]) : "r"(addr));
}
__device__ __forceinline__ void mma16816(float* c, const uint32_t* a, const uint32_t* b) {
    asm volatile("mma.sync.aligned.m16n8k16.row.col.f32.f16.f16.f32 "
        "{%0,%1,%2,%3}, {%4,%5,%6,%7}, {%8,%9}, {%0,%1,%2,%3};"
        : "+f"(c[0]), "+f"(c[1]), "+f"(c[2]), "+f"(c[3])
        : "r"(a[0]), "r"(a[1]), "r"(a[2]), "r"(a[3]), "r"(b[0]), "r"(b[1]));
}

// Smem row stride for 128-half rows: 136 halves (272 B) -> conflict-free ldmatrix
#define RS 136
#define TILE_HALFS (128 * RS)              // 17408 halves = 34816 B
#define SM_A 0
#define SM_B 34816
#define SM_V 69632                          // 256 floats
#define SM_TOT (69632 + 1024)

// ---------------------------------------------------------------------------
// HMMA flash kernel. 256 threads, 128-query tile; loop over 24 key tiles.
// A,Bm fp16 [B][N][C].  Scores = A·B^T / sqrt(C); no max subtraction
// (|score| <= ~5 -> exp safe in fp32).
// MODE 0: V = grid coords, out = softmax·grid - grid  (flow_pred)
// MODE 1: V = vsrc fp32 [B][2][N] (flow_pred), out = softmax·V  (flow)
// ---------------------------------------------------------------------------
template<int MODE>
__global__ void __launch_bounds__(256, 2) flash_hmma(
    const __half* __restrict__ A, const __half* __restrict__ Bm,
    const float* __restrict__ vsrc, float* __restrict__ out)
{
    extern __shared__ char smem[];
    __half* sA = (__half*)(smem + SM_A);
    __half* sB = (__half*)(smem + SM_B);
    float*  sV = (float*)(smem + SM_V);
    const uint32_t sbA = smem_u32(sA), sbB = smem_u32(sB);

    const int t = threadIdx.x, wid = t >> 5, lane = t & 31;
    const int b = blockIdx.y, n0 = blockIdx.x * 128;

    // Load 128x128 query tile (row stride RS halves)
    {
        const __half* src = A + ((size_t)b * NN + n0) * CH;
        #pragma unroll
        for (int it = 0; it < 8; it++) {
            int idx = it * 256 + t;          // 16B chunks: 128 rows x 16
            int r = idx >> 4, g = idx & 15;
            *(uint4*)(sA + r * RS + g * 8) = *(const uint4*)(src + (size_t)r * CH + g * 8);
        }
    }

    // Per-lane ldmatrix base addresses
    const int g8 = (lane >> 3) & 1, g16 = lane >> 4, l7 = lane & 7;
    const uint32_t aBase = sbA + (uint32_t)(((wid * 16 + l7 + g8 * 8) * RS + g16 * 8) * 2);
    const uint32_t bBase = sbB + (uint32_t)(((l7 + g16 * 8) * RS + g8 * 8) * 2);

    float L0 = 0.f, AX0 = 0.f, AY0 = 0.f, L1 = 0.f, AX1 = 0.f, AY1 = 0.f;
    const float scale = 0.088388347648318447f;  // 1/sqrt(128)

    for (int tile = 0; tile < NN / 128; tile++) {
        const int m0 = tile * 128;
        // Load key tile (+ V for MODE 1)
        {
            const __half* src = Bm + ((size_t)b * NN + m0) * CH;
            #pragma unroll
            for (int it = 0; it < 8; it++) {
                int idx = it * 256 + t;
                int r = idx >> 4, g = idx & 15;
                *(uint4*)(sB + r * RS + g * 8) = *(const uint4*)(src + (size_t)r * CH + g * 8);
            }
            if (MODE == 1) {
                if (t < 128) sV[t] = vsrc[(size_t)b * 2 * NN + m0 + t];
                else         sV[t] = vsrc[(size_t)b * 2 * NN + NN + m0 + (t - 128)];
            }
        }
        __syncthreads();

        // 16 queries x 128 keys per warp
        float c[16][4];
        #pragma unroll
        for (int j = 0; j < 16; j++)
            #pragma unroll
            for (int q = 0; q < 4; q++) c[j][q] = 0.f;

        #pragma unroll
        for (int k = 0; k < 8; k++) {
            uint32_t a[4];
            ldsm4(a, aBase + k * 32);
            #pragma unroll
            for (int j2 = 0; j2 < 8; j2++) {
                uint32_t bb[4];
                ldsm4(bb, bBase + j2 * (16 * RS * 2) + k * 32);
                mma16816(c[2 * j2],     a, bb);
                mma16816(c[2 * j2 + 1], a, bb + 2);
            }
        }

        // Softmax-accumulate (no max subtraction). Thread covers rows
        // (wid*16 + lane/4) and (+8), keys col = j*8 + (lane%4)*2 (+1).
        #pragma unroll
        for (int j = 0; j < 16; j++) {
            int colLocal = j * 8 + (lane & 3) * 2;
            float vx0, vy0, vx1, vy1;
            if (MODE == 0) {
                int m = m0 + colLocal;
                vx0 = (float)(m & (WW - 1));       vy0 = (float)(m >> 6);
                vx1 = (float)((m + 1) & (WW - 1)); vy1 = (float)((m + 1) >> 6);
            } else {
                float2 x2 = *(const float2*)&sV[colLocal];
                float2 y2 = *(const float2*)&sV[128 + colLocal];
                vx0 = x2.x; vx1 = x2.y; vy0 = y2.x; vy1 = y2.y;
            }
            float p0 = __expf(c[j][0] * scale);
            float p1 = __expf(c[j][1] * scale);
            float p2 = __expf(c[j][2] * scale);
            float p3 = __expf(c[j][3] * scale);
            L0  += p0 + p1;               L1  += p2 + p3;
            AX0 += p0 * vx0 + p1 * vx1;   AX1 += p2 * vx0 + p3 * vx1;
            AY0 += p0 * vy0 + p1 * vy1;   AY1 += p2 * vy0 + p3 * vy1;
        }
        __syncthreads();   // protect sB/sV before next tile's overwrite
    }

    // Reduce across the 4 lanes sharing each row (lane%4 = 0..3)
    #pragma unroll
    for (int o = 1; o <= 2; o <<= 1) {
        L0  += __shfl_xor_sync(0xffffffffu, L0,  o);
        AX0 += __shfl_xor_sync(0xffffffffu, AX0, o);
        AY0 += __shfl_xor_sync(0xffffffffu, AY0, o);
        L1  += __shfl_xor_sync(0xffffffffu, L1,  o);
        AX1 += __shfl_xor_sync(0xffffffffu, AX1, o);
        AY1 += __shfl_xor_sync(0xffffffffu, AY1, o);
    }
    if ((lane & 3) == 0) {
        int n_a = n0 + wid * 16 + (lane >> 2);
        int n_b = n_a + 8;
        float fxa = AX0 / L0, fya = AY0 / L0;
        float fxb = AX1 / L1, fyb = AY1 / L1;
        if (MODE == 0) {
            fxa -= (float)(n_a & (WW - 1)); fya -= (float)(n_a >> 6);
            fxb -= (float)(n_b & (WW - 1)); fyb -= (float)(n_b >> 6);
        }
        float* ob = out + (size_t)b * 2 * NN;
        ob[n_a] = fxa; ob[NN + n_a] = fya;
        ob[n_b] = fxb; ob[NN + n_b] = fyb;
    }
}

// ---------------------------------------------------------------------------
// Transpose + convert: fp32 [B][C][N] -> fp16 [B][N][C]
// ---------------------------------------------------------------------------
__global__ void __launch_bounds__(256) convH_kernel(
    const float* __restrict__ in, __half* __restrict__ out)
{
    __shared__ float tile[32][33];
    const int b = blockIdx.z, n0 = blockIdx.x * 32, c0 = blockIdx.y * 32;
    const int tx = threadIdx.x, ty = threadIdx.y;  // 32 x 8

    const float* ip = in + ((size_t)b * CH + c0) * NN + n0;
    #pragma unroll
    for (int i = 0; i < 4; i++) {
        int c = ty + i * 8;
        tile[c][tx] = ip[(size_t)c * NN + tx];
    }
    __syncthreads();
    __half* op = out + ((size_t)b * NN + n0) * CH + c0;
    #pragma unroll
    for (int i = 0; i < 4; i++) {
        int nr = ty + i * 8;
        op[(size_t)nr * CH + tx] = __float2half(tile[tx][nr]);
    }
}

// ---------------------------------------------------------------------------
// Projection: Y[co][n] = sum_ci X[ci][n] * W[co][ci] + bias[co]
// Writes fp32 [B][C][N] (YT) AND fp16 [B][N][C] (OH).
// ---------------------------------------------------------------------------
__global__ void __launch_bounds__(256) proj_kernel(
    const float* __restrict__ XT, const float* __restrict__ Wt,
    const float* __restrict__ bias, float* __restrict__ YT,
    __half* __restrict__ OH)
{
    __shared__ float Xs[64][64];
    __shared__ float Ws[64][64];

    const int b = blockIdx.z, n0 = blockIdx.x * 64, co0 = blockIdx.y * 64;
    const int t = threadIdx.x, tx = t & 15, ty = t >> 4;
    const float* Xb = XT + (size_t)b * CH * NN;

    float acc[4][4];
    #pragma unroll
    for (int i = 0; i < 4; i++)
        #pragma unroll
        for (int j = 0; j < 4; j++) acc[i][j] = 0.f;

    #pragma unroll
    for (int chk = 0; chk < 2; chk++) {
        __syncthreads();
        for (int idx = t; idx < 64 * 16; idx += 256) {
            int r = idx >> 4, g = idx & 15;
            *(float4*)(&Xs[r][g * 4]) =
                *(const float4*)(Xb + (size_t)(chk * 64 + r) * NN + n0 + g * 4);
        }
        for (int idx = t; idx < 64 * 16; idx += 256) {
            int co = idx >> 4, g = idx & 15;
            float4 w4 = *(const float4*)(Wt + (size_t)(co0 + co) * CH + chk * 64 + g * 4);
            Ws[g * 4 + 0][co] = w4.x; Ws[g * 4 + 1][co] = w4.y;
            Ws[g * 4 + 2][co] = w4.z; Ws[g * 4 + 3][co] = w4.w;
        }
        __syncthreads();
        #pragma unroll 4
        for (int c = 0; c < 64; c++) {
            float4 xa = *(const float4*)(&Xs[c][tx * 4]);
            float4 wa = *(const float4*)(&Ws[c][ty * 4]);
            acc[0][0] += wa.x * xa.x; acc[0][1] += wa.x * xa.y; acc[0][2] += wa.x * xa.z; acc[0][3] += wa.x * xa.w;
            acc[1][0] += wa.y * xa.x; acc[1][1] += wa.y * xa.y; acc[1][2] += wa.y * xa.z; acc[1][3] += wa.y * xa.w;
            acc[2][0] += wa.z * xa.x; acc[2][1] += wa.z * xa.y; acc[2][2] += wa.z * xa.z; acc[2][3] += wa.z * xa.w;
            acc[3][0] += wa.w * xa.x; acc[3][1] += wa.w * xa.y; acc[3][2] += wa.w * xa.z; acc[3][3] += wa.w * xa.w;
        }
    }

    float bv[4];
    #pragma unroll
    for (int i = 0; i < 4; i++) bv[i] = bias[co0 + ty * 4 + i];

    // fp32 transposed output [C][N]
    #pragma unroll
    for (int i = 0; i < 4; i++) {
        float4 o;
        o.x = acc[i][0] + bv[i]; o.y = acc[i][1] + bv[i];
        o.z = acc[i][2] + bv[i]; o.w = acc[i][3] + bv[i];
        *(float4*)(YT + (size_t)b * CH * NN + (size_t)(co0 + ty * 4 + i) * NN + n0 + tx * 4) = o;
    }
    // fp16 [N][C] output: per n (j), 4 consecutive co -> one 8B store
    #pragma unroll
    for (int j = 0; j < 4; j++) {
        int n = n0 + tx * 4 + j;
        __half h[4];
        #pragma unroll
        for (int i = 0; i < 4; i++) h[i] = __float2half(acc[i][j] + bv[i]);
        *(uint2*)(OH + ((size_t)b * NN + n) * CH + co0 + ty * 4) = *(uint2*)h;
    }
}

// ---------------------------------------------------------------------------
// Inputs: feature0, feature1, q_w, q_b, k_w, k_b, scale_idx
// Output: [flow | flow_pred], each [B,2,H,W] float32
// ---------------------------------------------------------------------------
extern "C" void kernel_launch(void* const* d_in, const int* in_sizes, int n_in,
                              void* d_out, int out_size)
{
    const float* f0 = (const float*)d_in[0];
    const float* f1 = (const float*)d_in[1];
    const float* qw = (const float*)d_in[2];
    const float* qb = (const float*)d_in[3];
    const float* kw = (const float*)d_in[4];
    const float* kb = (const float*)d_in[5];

    float* out       = (float*)d_out;
    float* flow      = out;
    float* flow_pred = out + (size_t)BATCH * 2 * NN;

    void* p;
    cudaGetSymbolAddress(&p, g_qT);  float* qT = (float*)p;
    cudaGetSymbolAddress(&p, g_kT);  float* kT = (float*)p;
    cudaGetSymbolAddress(&p, g_f0h); __half* f0h = (__half*)p;
    cudaGetSymbolAddress(&p, g_f1h); __half* f1h = (__half*)p;
    cudaGetSymbolAddress(&p, g_qh);  __half* qh  = (__half*)p;
    cudaGetSymbolAddress(&p, g_kh);  __half* kh  = (__half*)p;

    cudaFuncSetAttribute(flash_hmma<0>, cudaFuncAttributeMaxDynamicSharedMemorySize, SM_TOT);
    cudaFuncSetAttribute(flash_hmma<1>, cudaFuncAttributeMaxDynamicSharedMemorySize, SM_TOT);

    dim3 cgrid(NN / 32, CH / 32, BATCH);   // transpose/convert
    dim3 cblk(32, 8);
    dim3 fgrid(NN / 128, BATCH);           // flash: 24 x 8
    dim3 pgrid(NN / 64, CH / 64, BATCH);   // proj

    convH_kernel<<<cgrid, cblk>>>(f0, f0h);
    convH_kernel<<<cgrid, cblk>>>(f1, f1h);
    flash_hmma<0><<<fgrid, 256, SM_TOT>>>(f0h, f1h, nullptr, flow_pred);
    proj_kernel<<<pgrid, 256>>>(f0, qw, qb, qT, qh);
    proj_kernel<<<pgrid, 256>>>(qT, kw, kb, kT, kh);
    flash_hmma<1><<<fgrid, 256, SM_TOT>>>(qh, kh, flow_pred, flow);
}

// round 5
// speedup vs baseline: 5.6508x; 1.4791x over previous
#include <cuda_runtime.h>
#include <cuda_fp16.h>
#include <cstdint>

#define BATCH 8
#define CH    128
#define HH    48
#define WW    64
#define NN    (HH*WW)   // 3072

// scale*log2e folded into f1h and kh:  exp(score/sqrt(C)) = ex2(score * S2)
#define S2F ((float)(1.4426950408889634 * 0.088388347648318447))

// ---------------------------------------------------------------------------
// Scratch (__device__ globals; no allocation allowed)
// ---------------------------------------------------------------------------
__device__ __half g_f0h[BATCH*NN*CH];   // f0 fp16 [B][N][C]
__device__ __half g_f1h[BATCH*NN*CH];   // f1*S2 fp16 [B][N][C]
__device__ __half g_qh [BATCH*NN*CH];   // q fp16 [B][N][C]
__device__ __half g_kh [BATCH*NN*CH];   // k*S2 fp16 [B][N][C]

// ---------------------------------------------------------------------------
// Base-ISA helpers (sm_80-era only; no tcgen05 on this toolchain)
// ---------------------------------------------------------------------------
__device__ __forceinline__ uint32_t smem_u32(const void* p) {
    uint32_t a;
    asm("{ .reg .u64 t; cvta.to.shared.u64 t, %1; cvt.u32.u64 %0, t; }" : "=r"(a) : "l"(p));
    return a;
}
__device__ __forceinline__ void ldsm4(uint32_t* r, uint32_t addr) {
    asm volatile("ldmatrix.sync.aligned.m8n8.x4.shared.b16 {%0,%1,%2,%3}, [%4];"
        : "=r"(r[0]), "=r"(r[1]), "=r"(r[2]), "=r"(r[3]) : "r"(addr));
}
__device__ __forceinline__ void mma16816(float* c, const uint32_t* a, const uint32_t* b) {
    asm volatile("mma.sync.aligned.m16n8k16.row.col.f32.f16.f16.f32 "
        "{%0,%1,%2,%3}, {%4,%5,%6,%7}, {%8,%9}, {%0,%1,%2,%3};"
        : "+f"(c[0]), "+f"(c[1]), "+f"(c[2]), "+f"(c[3])
        : "r"(a[0]), "r"(a[1]), "r"(a[2]), "r"(a[3]), "r"(b[0]), "r"(b[1]));
}
__device__ __forceinline__ float ex2f(float x) {
    float y; asm("ex2.approx.f32 %0, %1;" : "=f"(y) : "f"(x)); return y;
}
#define CP16(dst, src) asm volatile("cp.async.cg.shared.global [%0], [%1], 16;" :: "r"(dst), "l"(src))
#define CP_COMMIT()    asm volatile("cp.async.commit_group;" ::: "memory")
#define CP_WAIT0()     asm volatile("cp.async.wait_group 0;" ::: "memory")

// Smem row stride: 136 halves (272 B) -> conflict-free ldmatrix
#define RS 136
#define TILE_B (128 * RS * 2)   // 34816

// Flash smem map (dynamic)
#define FSM_A    0
#define FSM_B0   34816
#define FSM_B1   69632
#define FSM_V0   104448
#define FSM_V1   105472
#define FSM_RED  106496          // 384 floats (cross-warp L/AX/AY reduction)
#define FSM_TOT  108032

// Proj smem map (dynamic)
#define PSM_F   0
#define PSM_W   34816
#define PSM_QB  69632
#define PSM_KB  70144
#define PSM_TOT 70656

// ---------------------------------------------------------------------------
// cp.async prefetch of one 128x128 fp16 tile into smem (RS stride)
// ---------------------------------------------------------------------------
__device__ __forceinline__ void prefetch_tile(uint32_t dstBase, const __half* src, int t) {
    #pragma unroll
    for (int it = 0; it < 8; it++) {
        int idx = it * 256 + t;
        int r = idx >> 4, g = idx & 15;
        CP16(dstBase + (uint32_t)((r * RS + g * 8) * 2), src + (size_t)r * CH + g * 8);
    }
}

// ---------------------------------------------------------------------------
// HMMA flash. 256 thr, 128-query tile, 24 key tiles, cp.async double buffer.
// Warp tile: 32 queries x 64 keys (wr = wid>>1 row block, wc = wid&1 key half).
// The wc=0/wc=1 warp pair covering the same rows is combined through smem
// at the end (this was the R4 bug: missing cross-warp softmax reduction).
// Scores pre-scaled (S2 folded into B operand) -> p = ex2(score).
// MODE 0: V = grid coords, out = softmax·grid - grid  (flow_pred)
// MODE 1: V = vsrc fp32 [B][2][N], out = softmax·V     (flow)
// ---------------------------------------------------------------------------
template<int MODE>
__global__ void __launch_bounds__(256, 2) flash_hmma(
    const __half* __restrict__ A, const __half* __restrict__ Bm,
    const float* __restrict__ vsrc, float* __restrict__ out)
{
    extern __shared__ char smem[];
    const uint32_t sb = smem_u32(smem);
    const int t = threadIdx.x, wid = t >> 5, lane = t & 31;
    const int wr = wid >> 1, wc = wid & 1;
    const int b = blockIdx.y, n0 = blockIdx.x * 128;
    const size_t vbase = (size_t)b * 2 * NN;

    // Query tile (plain stores; ordered by first-iteration __syncthreads)
    {
        __half* sA = (__half*)smem;
        const __half* src = A + ((size_t)b * NN + n0) * CH;
        #pragma unroll
        for (int it = 0; it < 8; it++) {
            int idx = it * 256 + t;
            int r = idx >> 4, g = idx & 15;
            *(uint4*)(sA + r * RS + g * 8) = *(const uint4*)(src + (size_t)r * CH + g * 8);
        }
    }

    // Prefetch key tile 0 (+V)
    const __half* Bbase = Bm + (size_t)b * NN * CH;
    prefetch_tile(sb + FSM_B0, Bbase, t);
    if (MODE == 1 && t < 64) {
        const float* s = (t < 32) ? (vsrc + vbase + t * 4)
                                  : (vsrc + vbase + NN + (t - 32) * 4);
        CP16(sb + FSM_V0 + t * 16, s);
    }
    CP_COMMIT();

    const int g8 = (lane >> 3) & 1, g16 = lane >> 4, l7 = lane & 7;
    const uint32_t aB0 = sb + FSM_A + (uint32_t)(((wr * 32 + l7 + g8 * 8) * RS + g16 * 8) * 2);
    const uint32_t aB1 = aB0 + (uint32_t)(16 * RS * 2);
    const uint32_t bOff = (uint32_t)(((wc * 64 + l7 + g16 * 8) * RS + g8 * 8) * 2);

    float L[2][2], AX[2][2], AY[2][2];
    #pragma unroll
    for (int i = 0; i < 2; i++)
        #pragma unroll
        for (int h = 0; h < 2; h++) { L[i][h] = 0.f; AX[i][h] = 0.f; AY[i][h] = 0.f; }

    const int tid4 = lane & 3;

    for (int tile = 0; tile < NN / 128; tile++) {
        const uint32_t cur = tile & 1;
        CP_WAIT0();
        __syncthreads();   // data visible + all warps done with the other buffer

        if (tile + 1 < NN / 128) {
            const int mn = (tile + 1) * 128;
            prefetch_tile(sb + (cur ? FSM_B0 : FSM_B1), Bbase + (size_t)mn * CH, t);
            if (MODE == 1 && t < 64) {
                const float* s = (t < 32) ? (vsrc + vbase + mn + t * 4)
                                          : (vsrc + vbase + NN + mn + (t - 32) * 4);
                CP16(sb + (cur ? FSM_V0 : FSM_V1) + t * 16, s);
            }
            CP_COMMIT();
        }

        const uint32_t bB = sb + (cur ? FSM_B1 : FSM_B0) + bOff;
        const float* sV = (const float*)(smem + (cur ? FSM_V1 : FSM_V0));

        float c[2][8][4];
        #pragma unroll
        for (int rb = 0; rb < 2; rb++)
            #pragma unroll
            for (int j = 0; j < 8; j++)
                #pragma unroll
                for (int q = 0; q < 4; q++) c[rb][j][q] = 0.f;

        #pragma unroll
        for (int k = 0; k < 8; k++) {
            uint32_t a0[4], a1[4];
            ldsm4(a0, aB0 + k * 32);
            ldsm4(a1, aB1 + k * 32);
            #pragma unroll
            for (int j2 = 0; j2 < 4; j2++) {
                uint32_t bb[4];
                ldsm4(bb, bB + j2 * (16 * RS * 2) + k * 32);
                mma16816(c[0][2 * j2],     a0, bb);
                mma16816(c[0][2 * j2 + 1], a0, bb + 2);
                mma16816(c[1][2 * j2],     a1, bb);
                mma16816(c[1][2 * j2 + 1], a1, bb + 2);
            }
        }

        // exp + accumulate
        #pragma unroll
        for (int rb = 0; rb < 2; rb++) {
            float Lt0 = 0.f, Lt1 = 0.f;   // tile-local row sums (MODE0 vy trick)
            #pragma unroll
            for (int j = 0; j < 8; j++) {
                float p0 = ex2f(c[rb][j][0]);
                float p1 = ex2f(c[rb][j][1]);
                float p2 = ex2f(c[rb][j][2]);
                float p3 = ex2f(c[rb][j][3]);
                if (MODE == 0) {
                    float vx0 = (float)(j * 8 + tid4 * 2);
                    float vx1 = vx0 + 1.f;
                    Lt0 += p0 + p1;  Lt1 += p2 + p3;
                    AX[rb][0] += p0 * vx0 + p1 * vx1;
                    AX[rb][1] += p2 * vx0 + p3 * vx1;
                } else {
                    int cl = wc * 64 + j * 8 + tid4 * 2;
                    float2 x2 = *(const float2*)&sV[cl];
                    float2 y2 = *(const float2*)&sV[128 + cl];
                    L[rb][0]  += p0 + p1;          L[rb][1]  += p2 + p3;
                    AX[rb][0] += p0 * x2.x + p1 * x2.y;
                    AX[rb][1] += p2 * x2.x + p3 * x2.y;
                    AY[rb][0] += p0 * y2.x + p1 * y2.y;
                    AY[rb][1] += p2 * y2.x + p3 * y2.y;
                }
            }
            if (MODE == 0) {
                float vy = (float)(2 * tile + wc);
                L[rb][0] += Lt0;  L[rb][1] += Lt1;
                AY[rb][0] += vy * Lt0;  AY[rb][1] += vy * Lt1;
            }
        }
    }

    // Reduce across the 4 lanes of each quad (they share the same rows)
    #pragma unroll
    for (int o = 1; o <= 2; o <<= 1)
        #pragma unroll
        for (int rb = 0; rb < 2; rb++)
            #pragma unroll
            for (int h = 0; h < 2; h++) {
                L[rb][h]  += __shfl_xor_sync(0xffffffffu, L[rb][h],  o);
                AX[rb][h] += __shfl_xor_sync(0xffffffffu, AX[rb][h], o);
                AY[rb][h] += __shfl_xor_sync(0xffffffffu, AY[rb][h], o);
            }

    // Cross-warp (wc pair) reduction through smem: wc=1 publishes partials,
    // wc=0 combines and writes the output. rl in [0,128) is the local row.
    float* red = (float*)(smem + FSM_RED);
    if (wc == 1 && tid4 == 0) {
        #pragma unroll
        for (int rb = 0; rb < 2; rb++)
            #pragma unroll
            for (int h = 0; h < 2; h++) {
                int rl = wr * 32 + rb * 16 + h * 8 + (lane >> 2);
                red[rl]       = L[rb][h];
                red[128 + rl] = AX[rb][h];
                red[256 + rl] = AY[rb][h];
            }
    }
    __syncthreads();
    if (wc == 0 && tid4 == 0) {
        float* ob = out + vbase;
        #pragma unroll
        for (int rb = 0; rb < 2; rb++)
            #pragma unroll
            for (int h = 0; h < 2; h++) {
                int rl = wr * 32 + rb * 16 + h * 8 + (lane >> 2);
                float Lt  = L[rb][h]  + red[rl];
                float AXt = AX[rb][h] + red[128 + rl];
                float AYt = AY[rb][h] + red[256 + rl];
                int n = n0 + rl;
                float fx = AXt / Lt, fy = AYt / Lt;
                if (MODE == 0) { fx -= (float)(n & (WW - 1)); fy -= (float)(n >> 6); }
                ob[n] = fx;  ob[NN + n] = fy;
            }
    }
}

// ---------------------------------------------------------------------------
// Fused projection (HMMA): per 128-row tile of f0h:
//   q = f0 @ qW^T + qb        -> fp16 [N][C]  (kept in regs as A-fragments)
//   k = (q @ kW^T + kb) * S2  -> fp16 [N][C]
// Per-warp tile: 16 rows x full 128 cols (no key split -> no reduction needed).
// ---------------------------------------------------------------------------
__global__ void __launch_bounds__(256) proj_fused(
    const __half* __restrict__ F0, const float* __restrict__ qw,
    const float* __restrict__ qb,  const float* __restrict__ kw,
    const float* __restrict__ kb,
    __half* __restrict__ QH, __half* __restrict__ KH)
{
    extern __shared__ char smem[];
    __half* sF = (__half*)(smem + PSM_F);
    __half* sW = (__half*)(smem + PSM_W);
    float* qbS = (float*)(smem + PSM_QB);
    float* kbS = (float*)(smem + PSM_KB);
    const uint32_t sbF = smem_u32(sF), sbW = smem_u32(sW);

    const int t = threadIdx.x, wid = t >> 5, lane = t & 31;
    const int b = blockIdx.y, n0 = blockIdx.x * 128;

    // f0h tile
    {
        const __half* src = F0 + ((size_t)b * NN + n0) * CH;
        #pragma unroll
        for (int it = 0; it < 8; it++) {
            int idx = it * 256 + t;
            int r = idx >> 4, g = idx & 15;
            *(uint4*)(sF + r * RS + g * 8) = *(const uint4*)(src + (size_t)r * CH + g * 8);
        }
    }
    // qW fp32 -> fp16 smem (rows = out-channel, cols = in-channel)
    #pragma unroll
    for (int it = 0; it < 16; it++) {
        int idx = it * 256 + t;
        int r = idx >> 5, g = idx & 31;
        float4 w = *(const float4*)(qw + (size_t)r * CH + g * 4);
        __half h[4] = {__float2half(w.x), __float2half(w.y), __float2half(w.z), __float2half(w.w)};
        *(uint2*)(sW + r * RS + g * 4) = *(uint2*)h;
    }
    if (t < 128) { qbS[t] = qb[t]; kbS[t] = kb[t]; }
    __syncthreads();

    const int g8 = (lane >> 3) & 1, g16 = lane >> 4, l7 = lane & 7, tid4 = lane & 3;
    const uint32_t aBase = sbF + (uint32_t)(((wid * 16 + l7 + g8 * 8) * RS + g16 * 8) * 2);
    const uint32_t bBase = sbW + (uint32_t)(((l7 + g16 * 8) * RS + g8 * 8) * 2);

    // ---- GEMM1: q = f0 @ qW^T ----
    float c[16][4];
    #pragma unroll
    for (int j = 0; j < 16; j++)
        #pragma unroll
        for (int q = 0; q < 4; q++) c[j][q] = 0.f;
    #pragma unroll
    for (int k = 0; k < 8; k++) {
        uint32_t a[4];
        ldsm4(a, aBase + k * 32);
        #pragma unroll
        for (int j2 = 0; j2 < 8; j2++) {
            uint32_t bb[4];
            ldsm4(bb, bBase + j2 * (16 * RS * 2) + k * 32);
            mma16816(c[2 * j2],     a, bb);
            mma16816(c[2 * j2 + 1], a, bb + 2);
        }
    }

    // add bias, pack fp16 (hq = A-fragments for GEMM2), store q
    uint32_t hq[16][2];
    const int r0 = wid * 16 + (lane >> 2);
    #pragma unroll
    for (int j = 0; j < 16; j++) {
        int col = j * 8 + tid4 * 2;
        float b0 = qbS[col], b1 = qbS[col + 1];
        __half2 v0 = __floats2half2_rn(c[j][0] + b0, c[j][1] + b1);
        __half2 v1 = __floats2half2_rn(c[j][2] + b0, c[j][3] + b1);
        hq[j][0] = *(uint32_t*)&v0;
        hq[j][1] = *(uint32_t*)&v1;
        *(uint32_t*)(QH + ((size_t)b * NN + n0 + r0) * CH + col)     = hq[j][0];
        *(uint32_t*)(QH + ((size_t)b * NN + n0 + r0 + 8) * CH + col) = hq[j][1];
    }

    __syncthreads();   // all ldsm of sW(qW) done
    // kW into sW
    #pragma unroll
    for (int it = 0; it < 16; it++) {
        int idx = it * 256 + t;
        int r = idx >> 5, g = idx & 31;
        float4 w = *(const float4*)(kw + (size_t)r * CH + g * 4);
        __half h[4] = {__float2half(w.x), __float2half(w.y), __float2half(w.z), __float2half(w.w)};
        *(uint2*)(sW + r * RS + g * 4) = *(uint2*)h;
    }
    __syncthreads();

    // ---- GEMM2: k = q @ kW^T  (A straight from hq fragments) ----
    float c2[16][4];
    #pragma unroll
    for (int j = 0; j < 16; j++)
        #pragma unroll
        for (int q = 0; q < 4; q++) c2[j][q] = 0.f;
    #pragma unroll
    for (int kk = 0; kk < 8; kk++) {
        uint32_t a[4] = { hq[2 * kk][0], hq[2 * kk][1], hq[2 * kk + 1][0], hq[2 * kk + 1][1] };
        #pragma unroll
        for (int j2 = 0; j2 < 8; j2++) {
            uint32_t bb[4];
            ldsm4(bb, bBase + j2 * (16 * RS * 2) + kk * 32);
            mma16816(c2[2 * j2],     a, bb);
            mma16816(c2[2 * j2 + 1], a, bb + 2);
        }
    }
    #pragma unroll
    for (int j = 0; j < 16; j++) {
        int col = j * 8 + tid4 * 2;
        float b0 = kbS[col], b1 = kbS[col + 1];
        __half2 v0 = __floats2half2_rn((c2[j][0] + b0) * S2F, (c2[j][1] + b1) * S2F);
        __half2 v1 = __floats2half2_rn((c2[j][2] + b0) * S2F, (c2[j][3] + b1) * S2F);
        *(uint32_t*)(KH + ((size_t)b * NN + n0 + r0) * CH + col)     = *(uint32_t*)&v0;
        *(uint32_t*)(KH + ((size_t)b * NN + n0 + r0 + 8) * CH + col) = *(uint32_t*)&v1;
    }
}

// ---------------------------------------------------------------------------
// Transpose + convert: fp32 [B][C][N] -> fp16 [B][N][C], times scale
// ---------------------------------------------------------------------------
__global__ void __launch_bounds__(256) convH_kernel(
    const float* __restrict__ in, __half* __restrict__ out, float scale)
{
    __shared__ float tile[32][33];
    const int b = blockIdx.z, n0 = blockIdx.x * 32, c0 = blockIdx.y * 32;
    const int tx = threadIdx.x, ty = threadIdx.y;  // 32 x 8

    const float* ip = in + ((size_t)b * CH + c0) * NN + n0;
    #pragma unroll
    for (int i = 0; i < 4; i++) {
        int c = ty + i * 8;
        tile[c][tx] = ip[(size_t)c * NN + tx];
    }
    __syncthreads();
    __half* op = out + ((size_t)b * NN + n0) * CH + c0;
    #pragma unroll
    for (int i = 0; i < 4; i++) {
        int nr = ty + i * 8;
        op[(size_t)nr * CH + tx] = __float2half(tile[tx][nr] * scale);
    }
}

// ---------------------------------------------------------------------------
// Inputs: feature0, feature1, q_w, q_b, k_w, k_b, scale_idx
// Output: [flow | flow_pred], each [B,2,H,W] float32
// ---------------------------------------------------------------------------
extern "C" void kernel_launch(void* const* d_in, const int* in_sizes, int n_in,
                              void* d_out, int out_size)
{
    const float* f0 = (const float*)d_in[0];
    const float* f1 = (const float*)d_in[1];
    const float* qw = (const float*)d_in[2];
    const float* qb = (const float*)d_in[3];
    const float* kw = (const float*)d_in[4];
    const float* kb = (const float*)d_in[5];

    float* out       = (float*)d_out;
    float* flow      = out;
    float* flow_pred = out + (size_t)BATCH * 2 * NN;

    void* p;
    cudaGetSymbolAddress(&p, g_f0h); __half* f0h = (__half*)p;
    cudaGetSymbolAddress(&p, g_f1h); __half* f1h = (__half*)p;
    cudaGetSymbolAddress(&p, g_qh);  __half* qh  = (__half*)p;
    cudaGetSymbolAddress(&p, g_kh);  __half* kh  = (__half*)p;

    cudaFuncSetAttribute(flash_hmma<0>, cudaFuncAttributeMaxDynamicSharedMemorySize, FSM_TOT);
    cudaFuncSetAttribute(flash_hmma<1>, cudaFuncAttributeMaxDynamicSharedMemorySize, FSM_TOT);
    cudaFuncSetAttribute(proj_fused,    cudaFuncAttributeMaxDynamicSharedMemorySize, PSM_TOT);

    dim3 cgrid(NN / 32, CH / 32, BATCH);
    dim3 cblk(32, 8);
    dim3 fgrid(NN / 128, BATCH);           // 24 x 8

    convH_kernel<<<cgrid, cblk>>>(f0, f0h, 1.0f);
    convH_kernel<<<cgrid, cblk>>>(f1, f1h, S2F);
    flash_hmma<0><<<fgrid, 256, FSM_TOT>>>(f0h, f1h, nullptr, flow_pred);
    proj_fused<<<fgrid, 256, PSM_TOT>>>(f0h, qw, qb, kw, kb, qh, kh);
    flash_hmma<1><<<fgrid, 256, FSM_TOT>>>(qh, kh, flow_pred, flow);
}

// round 6
// speedup vs baseline: 6.4189x; 1.1359x over previous
#include <cuda_runtime.h>
#include <cuda_fp16.h>
#include <cstdint>

#define BATCH 8
#define CH    128
#define HH    48
#define WW    64
#define NN    (HH*WW)   // 3072

#define S2F ((float)(1.4426950408889634 * 0.088388347648318447))

__device__ __half g_f0h[BATCH*NN*CH];
__device__ __half g_f1h[BATCH*NN*CH];
__device__ __half g_qh [BATCH*NN*CH];
__device__ __half g_kh [BATCH*NN*CH];

__device__ __forceinline__ uint32_t smem_u32(const void* p) {
    uint32_t a;
    asm("{ .reg .u64 t; cvta.to.shared.u64 t, %1; cvt.u32.u64 %0, t; }" : "=r"(a) : "l"(p));
    return a;
}
__device__ __forceinline__ void ldsm4(uint32_t* r, uint32_t addr) {
    asm volatile("ldmatrix.sync.aligned.m8n8.x4.shared.b16 {%0,%1,%2,%3}, [%4];"
        : "=r"(r[0]), "=r"(r[1]), "=r"(r[2]), "=r"(r[3]) : "r"(addr));
}
__device__ __forceinline__ void mma16816(float* c, const uint32_t* a, const uint32_t* b) {
    asm volatile("mma.sync.aligned.m16n8k16.row.col.f32.f16.f16.f32 "
        "{%0,%1,%2,%3}, {%4,%5,%6,%7}, {%8,%9}, {%0,%1,%2,%3};"
        : "+f"(c[0]), "+f"(c[1]), "+f"(c[2]), "+f"(c[3])
        : "r"(a[0]), "r"(a[1]), "r"(a[2]), "r"(a[3]), "r"(b[0]), "r"(b[1]));
}
__device__ __forceinline__ float ex2f(float x) {
    float y; asm("ex2.approx.f32 %0, %1;" : "=f"(y) : "f"(x)); return y;
}
#define CP16(dst, src) asm volatile("cp.async.cg.shared.global [%0], [%1], 16;" :: "r"(dst), "l"(src))
#define CP_COMMIT()    asm volatile("cp.async.commit_group;" ::: "memory")
#define CP_WAIT0()     asm volatile("cp.async.wait_group 0;" ::: "memory")

#define RS 136

#define FSM_A    0
#define FSM_B0   17408
#define FSM_B1   52224
#define FSM_V0   87040
#define FSM_V1   88064
#define FSM_RED  89088
#define FSM_TOT  90112

#define PSM_F   0
#define PSM_W   34816
#define PSM_QB  69632
#define PSM_KB  70144

__device__ __forceinline__ void prefetch_tile(uint32_t dstBase, const __half* src, int t) {
    #pragma unroll
    for (int it = 0; it < 8; it++) {
        int idx = it * 256 + t;
        int r = idx >> 4, g = idx & 15;
        CP16(dstBase + (uint32_t)((r * RS + g * 8) * 2), src + (size_t)r * CH + g * 8);
    }
}

template<int MODE>
__device__ __forceinline__ void flash_body(
    const __half* __restrict__ A, const __half* __restrict__ Bm,
    const float* __restrict__ vsrc, float* __restrict__ out,
    int b, int n0, char* smem)
{
    const uint32_t sb = smem_u32(smem);
    const int t = threadIdx.x, wid = t >> 5, lane = t & 31;
    const int wr = wid >> 1, wc = wid & 1;
    const size_t vbase = (size_t)b * 2 * NN;

    {
        __half* sA = (__half*)smem;
        const __half* src = A + ((size_t)b * NN + n0) * CH;
        #pragma unroll
        for (int it = 0; it < 4; it++) {
            int idx = it * 256 + t;
            int r = idx >> 4, g = idx & 15;
            *(uint4*)(sA + r * RS + g * 8) = *(const uint4*)(src + (size_t)r * CH + g * 8);
        }
    }

    const __half* Bbase = Bm + (size_t)b * NN * CH;
    prefetch_tile(sb + FSM_B0, Bbase, t);
    if (MODE == 1 && t < 64) {
        const float* s = (t < 32) ? (vsrc + vbase + t * 4)
                                  : (vsrc + vbase + NN + (t - 32) * 4);
        CP16(sb + FSM_V0 + t * 16, s);
    }
    CP_COMMIT();

    const int g8 = (lane >> 3) & 1, g16 = lane >> 4, l7 = lane & 7, tid4 = lane & 3;
    const uint32_t aBase = sb + FSM_A + (uint32_t)(((wr * 16 + l7 + g8 * 8) * RS + g16 * 8) * 2);
    const uint32_t bOff  = (uint32_t)(((wc * 64 + l7 + g16 * 8) * RS + g8 * 8) * 2);

    float L[2] = {0.f, 0.f}, AX[2] = {0.f, 0.f}, AY[2] = {0.f, 0.f};

    for (int tile = 0; tile < NN / 128; tile++) {
        const uint32_t cur = tile & 1;
        CP_WAIT0();
        __syncthreads();

        if (tile + 1 < NN / 128) {
            const int mn = (tile + 1) * 128;
            prefetch_tile(sb + (cur ? FSM_B0 : FSM_B1), Bbase + (size_t)mn * CH, t);
            if (MODE == 1 && t < 64) {
                const float* s = (t < 32) ? (vsrc + vbase + mn + t * 4)
                                          : (vsrc + vbase + NN + mn + (t - 32) * 4);
                CP16(sb + (cur ? FSM_V0 : FSM_V1) + t * 16, s);
            }
            CP_COMMIT();
        }

        const uint32_t bB = sb + (cur ? FSM_B1 : FSM_B0) + bOff;
        const float* sV = (const float*)(smem + (cur ? FSM_V1 : FSM_V0));

        float c[8][4];
        #pragma unroll
        for (int j = 0; j < 8; j++)
            #pragma unroll
            for (int q = 0; q < 4; q++) c[j][q] = 0.f;

        #pragma unroll
        for (int k = 0; k < 8; k++) {
            uint32_t a[4];
            ldsm4(a, aBase + k * 32);
            #pragma unroll
            for (int j2 = 0; j2 < 4; j2++) {
                uint32_t bb[4];
                ldsm4(bb, bB + j2 * (16 * RS * 2) + k * 32);
                mma16816(c[2 * j2],     a, bb);
                mma16816(c[2 * j2 + 1], a, bb + 2);
            }
        }

        float Lt0 = 0.f, Lt1 = 0.f;
        #pragma unroll
        for (int j = 0; j < 8; j++) {
            float p0 = ex2f(c[j][0]);
            float p1 = ex2f(c[j][1]);
            float p2 = ex2f(c[j][2]);
            float p3 = ex2f(c[j][3]);
            if (MODE == 0) {
                float vx0 = (float)(j * 8 + tid4 * 2);
                float vx1 = vx0 + 1.f;
                Lt0 += p0 + p1;  Lt1 += p2 + p3;
                AX[0] += p0 * vx0 + p1 * vx1;
                AX[1] += p2 * vx0 + p3 * vx1;
            } else {
                int cl = wc * 64 + j * 8 + tid4 * 2;
                float2 x2 = *(const float2*)&sV[cl];
                float2 y2 = *(const float2*)&sV[128 + cl];
                L[0]  += p0 + p1;          L[1]  += p2 + p3;
                AX[0] += p0 * x2.x + p1 * x2.y;
                AX[1] += p2 * x2.x + p3 * x2.y;
                AY[0] += p0 * y2.x + p1 * y2.y;
                AY[1] += p2 * y2.x + p3 * y2.y;
            }
        }
        if (MODE == 0) {
            float vy = (float)(2 * tile + wc);
            L[0] += Lt0;  L[1] += Lt1;
            AY[0] += vy * Lt0;  AY[1] += vy * Lt1;
        }
    }

    #pragma unroll
    for (int o = 1; o <= 2; o <<= 1)
        #pragma unroll
        for (int h = 0; h < 2; h++) {
            L[h]  += __shfl_xor_sync(0xffffffffu, L[h],  o);
            AX[h] += __shfl_xor_sync(0xffffffffu, AX[h], o);
            AY[h] += __shfl_xor_sync(0xffffffffu, AY[h], o);
        }

    float* red = (float*)(smem + FSM_RED);
    if (wc == 1 && tid4 == 0) {
        #pragma unroll
        for (int h = 0; h < 2; h++) {
            int rl = wr * 16 + h * 8 + (lane >> 2);
            red[rl]       = L[h];
            red[64 + rl]  = AX[h];
            red[128 + rl] = AY[h];
        }
    }
    __syncthreads();
    if (wc == 0 && tid4 == 0) {
        float* ob = out + vbase;
        #pragma unroll
        for (int h = 0; h < 2; h++) {
            int rl = wr * 16 + h * 8 + (lane >> 2);
            float Lt  = L[h]  + red[rl];
            float AXt = AX[h] + red[64 + rl];
            float AYt = AY[h] + red[128 + rl];
            int n = n0 + rl;
            float fx = AXt / Lt, fy = AYt / Lt;
            if (MODE == 0) { fx -= (float)(n & (WW - 1)); fy -= (float)(n >> 6); }
            ob[n] = fx;  ob[NN + n] = fy;
        }
    }
}

__device__ __forceinline__ void proj_body(
    const __half* __restrict__ F0, const float* __restrict__ qw,
    const float* __restrict__ qb,  const float* __restrict__ kw,
    const float* __restrict__ kb,
    __half* __restrict__ QH, __half* __restrict__ KH,
    int b, int n0, char* smem)
{
    __half* sF = (__half*)(smem + PSM_F);
    __half* sW = (__half*)(smem + PSM_W);
    float* qbS = (float*)(smem + PSM_QB);
    float* kbS = (float*)(smem + PSM_KB);
    const uint32_t sbF = smem_u32(sF), sbW = smem_u32(sW);

    const int t = threadIdx.x, wid = t >> 5, lane = t & 31;

    {
        const __half* src = F0 + ((size_t)b * NN + n0) * CH;
        #pragma unroll
        for (int it = 0; it < 8; it++) {
            int idx = it * 256 + t;
            int r = idx >> 4, g = idx & 15;
            *(uint4*)(sF + r * RS + g * 8) = *(const uint4*)(src + (size_t)r * CH + g * 8);
        }
    }
    #pragma unroll
    for (int it = 0; it < 16; it++) {
        int idx = it * 256 + t;
        int r = idx >> 5, g = idx & 31;
        float4 w = *(const float4*)(qw + (size_t)r * CH + g * 4);
        __half h[4] = {__float2half(w.x), __float2half(w.y), __float2half(w.z), __float2half(w.w)};
        *(uint2*)(sW + r * RS + g * 4) = *(uint2*)h;
    }
    if (t < 128) { qbS[t] = qb[t]; kbS[t] = kb[t]; }
    __syncthreads();

    const int g8 = (lane >> 3) & 1, g16 = lane >> 4, l7 = lane & 7, tid4 = lane & 3;
    const uint32_t aBase = sbF + (uint32_t)(((wid * 16 + l7 + g8 * 8) * RS + g16 * 8) * 2);
    const uint32_t bBase = sbW + (uint32_t)(((l7 + g16 * 8) * RS + g8 * 8) * 2);

    float c[16][4];
    #pragma unroll
    for (int j = 0; j < 16; j++)
        #pragma unroll
        for (int q = 0; q < 4; q++) c[j][q] = 0.f;
    #pragma unroll
    for (int k = 0; k < 8; k++) {
        uint32_t a[4];
        ldsm4(a, aBase + k * 32);
        #pragma unroll
        for (int j2 = 0; j2 < 8; j2++) {
            uint32_t bb[4];
            ldsm4(bb, bBase + j2 * (16 * RS * 2) + k * 32);
            mma16816(c[2 * j2],     a, bb);
            mma16816(c[2 * j2 + 1], a, bb + 2);
        }
    }

    uint32_t hq[16][2];
    const int r0 = wid * 16 + (lane >> 2);
    #pragma unroll
    for (int j = 0; j < 16; j++) {
        int col = j * 8 + tid4 * 2;
        float b0 = qbS[col], b1 = qbS[col + 1];
        __half2 v0 = __floats2half2_rn(c[j][0] + b0, c[j][1] + b1);
        __half2 v1 = __floats2half2_rn(c[j][2] + b0, c[j][3] + b1);
        hq[j][0] = *(uint32_t*)&v0;
        hq[j][1] = *(uint32_t*)&v1;
        *(uint32_t*)(QH + ((size_t)b * NN + n0 + r0) * CH + col)     = hq[j][0];
        *(uint32_t*)(QH + ((size_t)b * NN + n0 + r0 + 8) * CH + col) = hq[j][1];
    }

    __syncthreads();
    #pragma unroll
    for (int it = 0; it < 16; it++) {
        int idx = it * 256 + t;
        int r = idx >> 5, g = idx & 31;
        float4 w = *(const float4*)(kw + (size_t)r * CH + g * 4);
        __half h[4] = {__float2half(w.x), __float2half(w.y), __float2half(w.z), __float2half(w.w)};
        *(uint2*)(sW + r * RS + g * 4) = *(uint2*)h;
    }
    __syncthreads();

    float c2[16][4];
    #pragma unroll
    for (int j = 0; j < 16; j++)
        #pragma unroll
        for (int q = 0; q < 4; q++) c2[j][q] = 0.f;
    #pragma unroll
    for (int kk = 0; kk < 8; kk++) {
        uint32_t a[4] = { hq[2 * kk][0], hq[2 * kk][1], hq[2 * kk + 1][0], hq[2 * kk + 1][1] };
        #pragma unroll
        for (int j2 = 0; j2 < 8; j2++) {
            uint32_t bb[4];
            ldsm4(bb, bBase + j2 * (16 * RS * 2) + kk * 32);
            mma16816(c2[2 * j2],     a, bb);
            mma16816(c2[2 * j2 + 1], a, bb + 2);
        }
    }
    #pragma unroll
    for (int j = 0; j < 16; j++) {
        int col = j * 8 + tid4 * 2;
        float b0 = kbS[col], b1 = kbS[col + 1];
        __half2 v0 = __floats2half2_rn((c2[j][0] + b0) * S2F, (c2[j][1] + b1) * S2F);
        __half2 v1 = __floats2half2_rn((c2[j][2] + b0) * S2F, (c2[j][3] + b1) * S2F);
        *(uint32_t*)(KH + ((size_t)b * NN + n0 + r0) * CH + col)     = *(uint32_t*)&v0;
        *(uint32_t*)(KH + ((size_t)b * NN + n0 + r0 + 8) * CH + col) = *(uint32_t*)&v1;
    }
}

__global__ void __launch_bounds__(256, 2) stage0_kernel(
    const __half* __restrict__ f0h, const __half* __restrict__ f1h,
    const float* __restrict__ qw, const float* __restrict__ qb,
    const float* __restrict__ kw, const float* __restrict__ kb,
    __half* __restrict__ qh, __half* __restrict__ kh,
    float* __restrict__ flow_pred)
{
    extern __shared__ char smem[];
    if (blockIdx.y < 4) {                        // 192 proj CTAs, scheduled first
        int idx = blockIdx.y * 48 + blockIdx.x;  // 0..191
        proj_body(f0h, qw, qb, kw, kb, qh, kh, idx / 24, (idx % 24) * 128, smem);
    } else {
        flash_body<0>(f0h, f1h, nullptr, flow_pred,
                      blockIdx.y - 4, blockIdx.x * 64, smem);
    }
}

__global__ void __launch_bounds__(256, 2) stage1_kernel(
    const __half* __restrict__ qh, const __half* __restrict__ kh,
    const float* __restrict__ flow_pred, float* __restrict__ flow)
{
    extern __shared__ char smem[];
    flash_body<1>(qh, kh, flow_pred, flow, blockIdx.y, blockIdx.x * 64, smem);
}

__global__ void __launch_bounds__(256) convH2_kernel(
    const float* __restrict__ f0, const float* __restrict__ f1,
    __half* __restrict__ o0, __half* __restrict__ o1)
{
    __shared__ float tile[32][33];
    const int z = blockIdx.z, b = z & 7;
    const float* in = (z < 8) ? f0 : f1;
    __half* out = (z < 8) ? o0 : o1;
    const float scale = (z < 8) ? 1.0f : S2F;
    const int n0 = blockIdx.x * 32, c0 = blockIdx.y * 32;
    const int tx = threadIdx.x, ty = threadIdx.y;

    const float* ip = in + ((size_t)b * CH + c0) * NN + n0;
    #pragma unroll
    for (int i = 0; i < 4; i++) {
        int c = ty + i * 8;
        tile[c][tx] = ip[(size_t)c * NN + tx];
    }
    __syncthreads();
    __half* op = out + ((size_t)b * NN + n0) * CH + c0;
    #pragma unroll
    for (int i = 0; i < 4; i++) {
        int nr = ty + i * 8;
        op[(size_t)nr * CH + tx] = __float2half(tile[tx][nr] * scale);
    }
}

extern "C" void kernel_launch(void* const* d_in, const int* in_sizes, int n_in,
                              void* d_out, int out_size)
{
    const float* f0 = (const float*)d_in[0];
    const float* f1 = (const float*)d_in[1];
    const float* qw = (const float*)d_in[2];
    const float* qb = (const float*)d_in[3];
    const float* kw = (const float*)d_in[4];
    const float* kb = (const float*)d_in[5];

    float* out       = (float*)d_out;
    float* flow      = out;
    float* flow_pred = out + (size_t)BATCH * 2 * NN;

    void* p;
    cudaGetSymbolAddress(&p, g_f0h); __half* f0h = (__half*)p;
    cudaGetSymbolAddress(&p, g_f1h); __half* f1h = (__half*)p;
    cudaGetSymbolAddress(&p, g_qh);  __half* qh  = (__half*)p;
    cudaGetSymbolAddress(&p, g_kh);  __half* kh  = (__half*)p;

    cudaFuncSetAttribute(stage0_kernel, cudaFuncAttributeMaxDynamicSharedMemorySize, FSM_TOT);
    cudaFuncSetAttribute(stage1_kernel, cudaFuncAttributeMaxDynamicSharedMemorySize, FSM_TOT);

    dim3 cgrid(NN / 32, CH / 32, 2 * BATCH);
    dim3 cblk(32, 8);
    dim3 s0grid(NN / 64, BATCH + 4);
    dim3 s1grid(NN / 64, BATCH);

    convH2_kernel<<<cgrid, cblk>>>(f0, f1, f0h, f1h);
    stage0_kernel<<<s0grid, 256, FSM_TOT>>>(f0h, f1h, qw, qb, kw, kb, qh, kh, flow_pred);
    stage1_kernel<<<s1grid, 256, FSM_TOT>>>(qh, kh, flow_pred, flow);
}